// round 13
// baseline (speedup 1.0000x reference)
#include <cuda_runtime.h>
#include <cuda_fp16.h>
#include <math.h>
#include <stdint.h>
#include <mma.h>

using namespace nvcuda;

#define BATCH 4
#define SEQ   1024
#define DMODEL 4096
#define KVDIM 512
#define NHEAD 32
#define HDIM  128
#define MROWS (BATCH*SEQ)   // 4096

// ---------------- scratch ----------------
__device__ float g_Q[MROWS * DMODEL];
__device__ float g_KV[MROWS * 2 * KVDIM];
__device__ __half g_x[MROWS * DMODEL];
__device__ __half g_wq[DMODEL * DMODEL];
__device__ __half g_wkv[DMODEL * 2 * KVDIM];
__device__ __half g_wo[DMODEL * DMODEL];
__device__ __half g_Qh[MROWS * DMODEL], g_Ql[MROWS * DMODEL];
__device__ __half g_Kh[MROWS * KVDIM];
__device__ __half g_Vh[MROWS * KVDIM];
__device__ __half g_o[MROWS * DMODEL];

// ---------------- fp32 -> fp16 ----------------
__global__ void conv_half_kernel(const float* __restrict__ src,
                                 __half* __restrict__ dst, int n4)
{
    int idx = blockIdx.x * blockDim.x + threadIdx.x;
    if (idx >= n4) return;
    float4 v = ((const float4*)src)[idx];
    ((__half2*)dst)[idx * 2]     = __halves2half2(__float2half(v.x), __float2half(v.y));
    ((__half2*)dst)[idx * 2 + 1] = __halves2half2(__float2half(v.z), __float2half(v.w));
}

__global__ void conv_half_pack_kernel(const float* __restrict__ src,
                                      __half* __restrict__ dst, int coloff, int n4)
{
    int idx = blockIdx.x * blockDim.x + threadIdx.x;
    if (idx >= n4) return;
    int r = idx >> 7, c4 = (idx & 127) << 2;
    float4 v = ((const float4*)src)[idx];
    __half* d = dst + (size_t)r * 1024 + coloff + c4;
    ((__half2*)d)[0] = __halves2half2(__float2half(v.x), __float2half(v.y));
    ((__half2*)d)[1] = __halves2half2(__float2half(v.z), __float2half(v.w));
}

// ---------------- cp.async helper ----------------
__device__ __forceinline__ void cp16(void* s, const void* g)
{
    uint32_t sa = (uint32_t)__cvta_generic_to_shared(s);
    asm volatile("cp.async.cg.shared.global [%0], [%1], 16;\n" :: "r"(sa), "l"(g));
}

// ---------------- fp16 GEMM: C = A[M,K] * B[K,N], fp32 acc ----------------
#define SA_LD 40
#define SB_LD 136
#define STAGE_H (128*SA_LD + 32*SB_LD)
#define GEMM_SMEM (3 * STAGE_H * 2)

__global__ void __launch_bounds__(256) gemm1_kernel(
    const __half* __restrict__ A, const __half* __restrict__ B,
    float* __restrict__ C, int Nn, int K)
{
    extern __shared__ __half smh[];
    const int bm = blockIdx.y * 128;
    const int bn = blockIdx.x * 128;
    const int tid = threadIdx.x;
    const int warp = tid >> 5;
    const int wr = (warp >> 2) * 64;
    const int wc = (warp & 3) * 32;

    wmma::fragment<wmma::accumulator, 16, 16, 16, float> acc[4][2];
    #pragma unroll
    for (int i = 0; i < 4; i++)
        #pragma unroll
        for (int j = 0; j < 2; j++)
            wmma::fill_fragment(acc[i][j], 0.0f);

    auto load_st = [&](int kt) {
        __half* s = smh + (kt % 3) * STAGE_H;
        int k0 = kt << 5;
        #pragma unroll
        for (int it = 0; it < 2; ++it) {
            int v = tid + it * 256;
            int r = v >> 2, c = (v & 3) << 3;
            cp16(s + r * SA_LD + c, A + (size_t)(bm + r) * K + k0 + c);
            int rb = v >> 4, cb = (v & 15) << 3;
            cp16(s + 128 * SA_LD + rb * SB_LD + cb,
                 B + (size_t)(k0 + rb) * Nn + bn + cb);
        }
        asm volatile("cp.async.commit_group;\n");
    };

    const int nt = K >> 5;
    load_st(0);
    load_st(1);

    for (int kt = 0; kt < nt; ++kt) {
        if (kt + 1 < nt)
            asm volatile("cp.async.wait_group 1;\n");
        else
            asm volatile("cp.async.wait_group 0;\n");
        __syncthreads();
        if (kt + 2 < nt) load_st(kt + 2);

        __half* s  = smh + (kt % 3) * STAGE_H;
        __half* sA = s;
        __half* sB = s + 128 * SA_LD;

        #pragma unroll
        for (int kk = 0; kk < 32; kk += 16) {
            wmma::fragment<wmma::matrix_b, 16, 16, 16, __half, wmma::row_major> b[2];
            #pragma unroll
            for (int j = 0; j < 2; j++)
                wmma::load_matrix_sync(b[j], sB + kk * SB_LD + wc + j * 16, SB_LD);
            #pragma unroll
            for (int i = 0; i < 4; i++) {
                wmma::fragment<wmma::matrix_a, 16, 16, 16, __half, wmma::row_major> a;
                wmma::load_matrix_sync(a, sA + (wr + i * 16) * SA_LD + kk, SA_LD);
                #pragma unroll
                for (int j = 0; j < 2; j++)
                    wmma::mma_sync(acc[i][j], a, b[j], acc[i][j]);
            }
        }
        __syncthreads();
    }

    #pragma unroll
    for (int i = 0; i < 4; i++)
        #pragma unroll
        for (int j = 0; j < 2; j++)
            wmma::store_matrix_sync(C + (size_t)(bm + wr + i * 16) * Nn + bn + wc + j * 16,
                                    acc[i][j], Nn, wmma::mem_row_major);
}

// ---------------- bias add (fp32 in place) ----------------
__global__ void bias_add4_kernel(float* __restrict__ X, const float* __restrict__ b,
                                 int width, int total4)
{
    int idx = blockIdx.x * blockDim.x + threadIdx.x;
    if (idx >= total4) return;
    int c = (idx << 2) % width;
    float4 v = ((float4*)X)[idx];
    float4 bb = *(const float4*)(b + c);
    v.x += bb.x; v.y += bb.y; v.z += bb.z; v.w += bb.w;
    ((float4*)X)[idx] = v;
}

// ---------------- RoPE + bias -> fp16 hi/lo (for Q) ----------------
__global__ void rope_q_kernel(const float* __restrict__ X, const float* __restrict__ bias,
                              __half* __restrict__ Oh, __half* __restrict__ Ol,
                              int width, float scale, int total_pairs)
{
    int idx = blockIdx.x * blockDim.x + threadIdx.x;
    if (idx >= total_pairs) return;
    int ppr = width >> 1;
    int row = idx / ppr;
    int p = idx - row * ppr;
    int i = p & 63;
    int pos = row & (SEQ - 1);
    float freq = exp2f(-(float)i * 0.20762050593434293f);
    float ang = (float)pos * freq;
    float sv, cv;
    sincosf(ang, &sv, &cv);
    float2 q = *(const float2*)(X + (size_t)row * width + 2 * p);
    float e = q.x + bias[2 * p];
    float o = q.y + bias[2 * p + 1];
    float re = (e * cv - o * sv) * scale;
    float ro = (o * cv + e * sv) * scale;
    __half he = __float2half(re), ho = __float2half(ro);
    size_t off = (size_t)row * width + 2 * p;
    *(__half2*)(Oh + off) = __halves2half2(he, ho);
    *(__half2*)(Ol + off) = __halves2half2(
        __float2half(re - __half2float(he)), __float2half(ro - __half2float(ho)));
}

// ---------------- RoPE + bias -> fp16 for K ----------------
__global__ void rope_k_kernel(const float* __restrict__ KV, const float* __restrict__ bias,
                              __half* __restrict__ O, int total_pairs)
{
    int idx = blockIdx.x * blockDim.x + threadIdx.x;
    if (idx >= total_pairs) return;
    int row = idx >> 8;
    int p = idx & 255;
    int i = p & 63;
    int pos = row & (SEQ - 1);
    float freq = exp2f(-(float)i * 0.20762050593434293f);
    float ang = (float)pos * freq;
    float sv, cv;
    sincosf(ang, &sv, &cv);
    float2 q = *(const float2*)(KV + (size_t)row * 1024 + 2 * p);
    float e = q.x + bias[2 * p];
    float o = q.y + bias[2 * p + 1];
    *(__half2*)(O + (size_t)row * KVDIM + 2 * p) = __halves2half2(
        __float2half(e * cv - o * sv), __float2half(o * cv + e * sv));
}

// ---------------- bias -> fp16 for V ----------------
__global__ void bias_v_kernel(const float* __restrict__ KV, const float* __restrict__ b,
                              __half* __restrict__ O, int n4)
{
    int idx = blockIdx.x * blockDim.x + threadIdx.x;
    if (idx >= n4) return;
    int r = idx >> 7, c4 = (idx & 127) << 2;
    float4 v = *(const float4*)(KV + (size_t)r * 1024 + 512 + c4);
    float4 bb = *(const float4*)(b + c4);
    __half* d = O + (size_t)r * KVDIM + c4;
    ((__half2*)d)[0] = __halves2half2(__float2half(v.x + bb.x), __float2half(v.y + bb.y));
    ((__half2*)d)[1] = __halves2half2(__float2half(v.z + bb.z), __float2half(v.w + bb.w));
}

// ---------------- fast exp on FMA pipe ----------------
__device__ __forceinline__ float fexp(float x)
{
    float y = x * 1.4426950408889634f;
    float r = __fadd_rn(y, 12582912.0f);
    float n = __fadd_rn(r, -12582912.0f);
    float f = y - n;
    int e = __float2int_rn(n);
    e = max(e, -126); e = min(e, 126);
    float t = f * 0.6931471805599453f;
    float p = __fmaf_rn(t, 0.0083333333f, 0.041666667f);
    p = __fmaf_rn(t, p, 0.16666667f);
    p = __fmaf_rn(t, p, 0.5f);
    p = __fmaf_rn(t, p, 1.0f);
    p = __fmaf_rn(t, p, 1.0f);
    return p * __int_as_float((e + 127) << 23);
}

// ---------------- tensor-core flash attention (256 threads, per-batch) ------
#define AQ_LD 136
#define AS_LD 72
#define OQH 0
#define OQL (OQH + 64*AQ_LD*2)
#define OKK (OQL + 64*AQ_LD*2)
#define OVV (OKK + 2*64*AQ_LD*2)
#define OPP (OVV + 2*64*AQ_LD*2)
#define OSS (OPP + 64*AS_LD*2)
#define OTT (OSS + 64*AS_LD*4)
#define OOO (OTT + 64*AQ_LD*4)
#define ATT_SMEM (OOO + 64*128*4)

__global__ void __launch_bounds__(256) attn_tc_kernel(
    const __half* __restrict__ Qh, const __half* __restrict__ Ql,
    const __half* __restrict__ K, const __half* __restrict__ V,
    __half* __restrict__ O, int b)
{
    extern __shared__ char smc[];
    __half* sQh = (__half*)(smc + OQH);
    __half* sQl = (__half*)(smc + OQL);
    __half* sK  = (__half*)(smc + OKK);
    __half* sV  = (__half*)(smc + OVV);
    __half* sP  = (__half*)(smc + OPP);
    float*  sS  = (float*)(smc + OSS);
    float*  sT  = (float*)(smc + OTT);
    float*  sO  = (float*)(smc + OOO);

    const int h = blockIdx.y;
    const int kh = h & 3;
    const int q0 = blockIdx.x * 64;
    const int tid = threadIdx.x;
    const int warp = tid >> 5;

    const int wrow = (warp >> 1) * 16;
    const int wch  = (warp & 1) * 32;
    const int pch  = (warp & 1) * 64;
    const int srow = tid >> 2;
    const int quad = tid & 3;

    #pragma unroll
    for (int it = 0; it < 4; it++) {
        int idx = tid + it * 256;
        int r = idx >> 4, c = (idx & 15) << 3;
        size_t go = (size_t)(b * SEQ + q0 + r) * DMODEL + h * HDIM + c;
        *(uint4*)(sQh + r * AQ_LD + c) = *(const uint4*)(Qh + go);
        *(uint4*)(sQl + r * AQ_LD + c) = *(const uint4*)(Ql + go);
    }
    #pragma unroll
    for (int it = 0; it < 8; it++) {
        ((float4*)sO)[tid + it * 256] = make_float4(0.f, 0.f, 0.f, 0.f);
    }

    auto prefetch = [&](int j) {
        int buf = j & 1;
        int k0 = j * 64;
        __half* dk = sK + buf * 64 * AQ_LD;
        __half* dv = sV + buf * 64 * AQ_LD;
        #pragma unroll
        for (int i = 0; i < 4; i++) {
            int idx = tid + i * 256;
            int r = idx >> 4, c = (idx & 15) << 3;
            size_t go = (size_t)(b * SEQ + k0 + r) * KVDIM + kh * HDIM + c;
            cp16(dk + r * AQ_LD + c, K + go);
            cp16(dv + r * AQ_LD + c, V + go);
        }
        asm volatile("cp.async.commit_group;\n");
    };

    prefetch(0);

    float mrow = -1e30f, lrow = 0.f;

    const int jmax = blockIdx.x;
    for (int j = 0; j <= jmax; ++j) {
        asm volatile("cp.async.wait_group 0;\n");
        __syncthreads();
        if (j + 1 <= jmax) prefetch(j + 1);

        __half* cK = sK + (j & 1) * 64 * AQ_LD;
        __half* cV = sV + (j & 1) * 64 * AQ_LD;

        {
            wmma::fragment<wmma::accumulator, 16, 16, 16, float> acc[2];
            wmma::fill_fragment(acc[0], 0.f);
            wmma::fill_fragment(acc[1], 0.f);
            #pragma unroll
            for (int ks = 0; ks < 8; ks++) {
                wmma::fragment<wmma::matrix_a, 16, 16, 16, __half, wmma::row_major> ah, al;
                wmma::load_matrix_sync(ah, sQh + wrow * AQ_LD + ks * 16, AQ_LD);
                wmma::load_matrix_sync(al, sQl + wrow * AQ_LD + ks * 16, AQ_LD);
                #pragma unroll
                for (int nf = 0; nf < 2; nf++) {
                    wmma::fragment<wmma::matrix_b, 16, 16, 16, __half, wmma::col_major> bf;
                    wmma::load_matrix_sync(bf, cK + (wch + nf * 16) * AQ_LD + ks * 16, AQ_LD);
                    wmma::mma_sync(acc[nf], ah, bf, acc[nf]);
                    wmma::mma_sync(acc[nf], al, bf, acc[nf]);
                }
            }
            #pragma unroll
            for (int nf = 0; nf < 2; nf++)
                wmma::store_matrix_sync(sS + wrow * AS_LD + wch + nf * 16, acc[nf],
                                        AS_LD, wmma::mem_row_major);
        }
        __syncthreads();

        float alpha;
        {
            const int cbase = quad * 16;
            const bool diag = (j == jmax);
            float sv[16];
            float mx = -1e30f;
            #pragma unroll
            for (int c = 0; c < 16; c++) {
                float s = sS[srow * AS_LD + cbase + c];
                if (diag && (cbase + c > srow)) s = -1e30f;
                sv[c] = s;
                mx = fmaxf(mx, s);
            }
            mx = fmaxf(mx, __shfl_xor_sync(0xffffffffu, mx, 1));
            mx = fmaxf(mx, __shfl_xor_sync(0xffffffffu, mx, 2));
            float mnew = fmaxf(mrow, mx);
            alpha = fexp(mrow - mnew);
            float sum = 0.f;
            #pragma unroll
            for (int c = 0; c < 16; c++) {
                float p = fexp(sv[c] - mnew);
                sP[srow * AS_LD + cbase + c] = __float2half(p);
                sum += p;
            }
            sum += __shfl_xor_sync(0xffffffffu, sum, 1);
            sum += __shfl_xor_sync(0xffffffffu, sum, 2);
            lrow = lrow * alpha + sum;
            mrow = mnew;
        }
        __syncthreads();

        {
            wmma::fragment<wmma::accumulator, 16, 16, 16, float> acc[4];
            #pragma unroll
            for (int nf = 0; nf < 4; nf++) wmma::fill_fragment(acc[nf], 0.f);
            #pragma unroll
            for (int kf = 0; kf < 4; kf++) {
                wmma::fragment<wmma::matrix_a, 16, 16, 16, __half, wmma::row_major> af;
                wmma::load_matrix_sync(af, sP + wrow * AS_LD + kf * 16, AS_LD);
                #pragma unroll
                for (int nf = 0; nf < 4; nf++) {
                    wmma::fragment<wmma::matrix_b, 16, 16, 16, __half, wmma::row_major> bf;
                    wmma::load_matrix_sync(bf, cV + kf * 16 * AQ_LD + pch + nf * 16, AQ_LD);
                    wmma::mma_sync(acc[nf], af, bf, acc[nf]);
                }
            }
            #pragma unroll
            for (int nf = 0; nf < 4; nf++)
                wmma::store_matrix_sync(sT + wrow * AQ_LD + pch + nf * 16, acc[nf],
                                        AQ_LD, wmma::mem_row_major);
        }
        __syncthreads();

        {
            const int c0 = quad * 32;
            #pragma unroll
            for (int c = 0; c < 32; c += 4) {
                float4 o = *(float4*)(sO + srow * 128 + c0 + c);
                float4 t = *(float4*)(sT + srow * AQ_LD + c0 + c);
                o.x = o.x * alpha + t.x; o.y = o.y * alpha + t.y;
                o.z = o.z * alpha + t.z; o.w = o.w * alpha + t.w;
                *(float4*)(sO + srow * 128 + c0 + c) = o;
            }
        }
        __syncthreads();
    }

    {
        float inv = 1.f / lrow;
        const int c0 = quad * 32;
        size_t off = (size_t)(b * SEQ + q0 + srow) * DMODEL + h * HDIM + c0;
        #pragma unroll
        for (int c = 0; c < 32; c += 2) {
            float2 o = *(float2*)(sO + srow * 128 + c0 + c);
            *(__half2*)(O + off + c) = __halves2half2(
                __float2half(o.x * inv), __float2half(o.y * inv));
        }
    }
}

// ---------------- launch ----------------
extern "C" void kernel_launch(void* const* d_in, const int* in_sizes, int n_in,
                              void* d_out, int out_size)
{
    const float* x  = (const float*)d_in[0];
    const float* Wq = (const float*)d_in[1];
    const float* bq = (const float*)d_in[2];
    const float* Wk = (const float*)d_in[3];
    const float* bk = (const float*)d_in[4];
    const float* Wv = (const float*)d_in[5];
    const float* bv = (const float*)d_in[6];
    const float* Wo = (const float*)d_in[7];
    const float* bo = (const float*)d_in[8];
    float* out = (float*)d_out;

    float *Qp, *KVp;
    __half *xp, *wq, *wkv, *wo, *op, *qh, *ql, *kk, *vv;
    cudaGetSymbolAddress((void**)&Qp, g_Q);
    cudaGetSymbolAddress((void**)&KVp, g_KV);
    cudaGetSymbolAddress((void**)&xp, g_x);
    cudaGetSymbolAddress((void**)&wq, g_wq);
    cudaGetSymbolAddress((void**)&wkv, g_wkv);
    cudaGetSymbolAddress((void**)&wo, g_wo);
    cudaGetSymbolAddress((void**)&op, g_o);
    cudaGetSymbolAddress((void**)&qh, g_Qh); cudaGetSymbolAddress((void**)&ql, g_Ql);
    cudaGetSymbolAddress((void**)&kk, g_Kh); cudaGetSymbolAddress((void**)&vv, g_Vh);

    cudaFuncSetAttribute(gemm1_kernel, cudaFuncAttributeMaxDynamicSharedMemorySize, GEMM_SMEM);
    cudaFuncSetAttribute(attn_tc_kernel, cudaFuncAttributeMaxDynamicSharedMemorySize, ATT_SMEM);

    cudaStream_t s1;
    cudaStreamCreate(&s1);
    cudaEvent_t eFork, eJoin, eAtt[BATCH];
    cudaEventCreateWithFlags(&eFork, cudaEventDisableTiming);
    cudaEventCreateWithFlags(&eJoin, cudaEventDisableTiming);
    for (int i = 0; i < BATCH; i++)
        cudaEventCreateWithFlags(&eAtt[i], cudaEventDisableTiming);

    // x conversion (needed by both chains)
    {
        int n4 = MROWS * DMODEL / 4;
        conv_half_kernel<<<(n4 + 255) / 256, 256>>>(x, xp, n4);
    }

    // fork
    cudaEventRecord(eFork, 0);
    cudaStreamWaitEvent(s1, eFork, 0);

    const float scale = 0.08838834764831843f;

    // default stream: Wq conv -> Q gemm -> rope_q
    {
        int n4 = DMODEL * DMODEL / 4;
        conv_half_kernel<<<(n4 + 255) / 256, 256>>>(Wq, wq, n4);
    }
    gemm1_kernel<<<dim3(DMODEL / 128, MROWS / 128), 256, GEMM_SMEM>>>(
        xp, wq, Qp, DMODEL, DMODEL);
    {
        int tpQ = MROWS * (DMODEL / 2);
        rope_q_kernel<<<(tpQ + 255) / 256, 256>>>(Qp, bq, qh, ql, DMODEL, scale, tpQ);
    }

    // s1: Wk/Wv pack -> KV gemm -> rope_k, bias_v, Wo conv
    {
        int n4 = DMODEL * KVDIM / 4;
        conv_half_pack_kernel<<<(n4 + 255) / 256, 256, 0, s1>>>(Wk, wkv, 0,   n4);
        conv_half_pack_kernel<<<(n4 + 255) / 256, 256, 0, s1>>>(Wv, wkv, 512, n4);
    }
    gemm1_kernel<<<dim3(1024 / 128, MROWS / 128), 256, GEMM_SMEM, s1>>>(
        xp, wkv, KVp, 1024, DMODEL);
    {
        int tpK = MROWS * 256;
        rope_k_kernel<<<(tpK + 255) / 256, 256, 0, s1>>>(KVp, bk, kk, tpK);
        int n4v = MROWS * KVDIM / 4;
        bias_v_kernel<<<(n4v + 255) / 256, 256, 0, s1>>>(KVp, bv, vv, n4v);
        int n4o = DMODEL * DMODEL / 4;
        conv_half_kernel<<<(n4o + 255) / 256, 256, 0, s1>>>(Wo, wo, n4o);
    }

    // join
    cudaEventRecord(eJoin, s1);
    cudaStreamWaitEvent(0, eJoin, 0);

    // attention per batch (stream 0), O-proj per batch (s1) overlapped
    for (int b = 0; b < BATCH; b++) {
        attn_tc_kernel<<<dim3(SEQ / 64, NHEAD), 256, ATT_SMEM>>>(qh, ql, kk, vv, op, b);
        cudaEventRecord(eAtt[b], 0);
        cudaStreamWaitEvent(s1, eAtt[b], 0);

        const __half* Aseg = op + (size_t)b * SEQ * DMODEL;
        float* Cseg = out + (size_t)b * SEQ * DMODEL;
        gemm1_kernel<<<dim3(DMODEL / 128, SEQ / 128), 256, GEMM_SMEM, s1>>>(
            Aseg, wo, Cseg, DMODEL, DMODEL);
        int t4 = SEQ * DMODEL / 4;
        bias_add4_kernel<<<(t4 + 255) / 256, 256, 0, s1>>>(Cseg, bo, DMODEL, t4);
    }

    // final join back to stream 0 so graph end depends on all work
    cudaEventRecord(eJoin, s1);
    cudaStreamWaitEvent(0, eJoin, 0);

    cudaEventDestroy(eFork);
    cudaEventDestroy(eJoin);
    for (int i = 0; i < BATCH; i++) cudaEventDestroy(eAtt[i]);
    cudaStreamDestroy(s1);
}

// round 14
// speedup vs baseline: 1.3070x; 1.3070x over previous
#include <cuda_runtime.h>
#include <cuda_fp16.h>
#include <math.h>
#include <stdint.h>
#include <mma.h>

using namespace nvcuda;

#define BATCH 4
#define SEQ   1024
#define DMODEL 4096
#define KVDIM 512
#define NHEAD 32
#define HDIM  128
#define MROWS (BATCH*SEQ)   // 4096

// ---------------- scratch ----------------
__device__ float g_Q[MROWS * DMODEL];
__device__ float g_KV[MROWS * 2 * KVDIM];
__device__ __half g_x[MROWS * DMODEL];
__device__ __half g_wq[DMODEL * DMODEL];
__device__ __half g_wkv[DMODEL * 2 * KVDIM];
__device__ __half g_wo[DMODEL * DMODEL];
__device__ __half g_Qh[MROWS * DMODEL], g_Ql[MROWS * DMODEL];
__device__ __half g_Kh[MROWS * KVDIM];
__device__ __half g_Vh[MROWS * KVDIM];
__device__ __half g_o[MROWS * DMODEL];

// ---------------- fp32 -> fp16 ----------------
__global__ void conv_half_kernel(const float* __restrict__ src,
                                 __half* __restrict__ dst, int n4)
{
    int idx = blockIdx.x * blockDim.x + threadIdx.x;
    if (idx >= n4) return;
    float4 v = ((const float4*)src)[idx];
    ((__half2*)dst)[idx * 2]     = __halves2half2(__float2half(v.x), __float2half(v.y));
    ((__half2*)dst)[idx * 2 + 1] = __halves2half2(__float2half(v.z), __float2half(v.w));
}

__global__ void conv_half_pack_kernel(const float* __restrict__ src,
                                      __half* __restrict__ dst, int coloff, int n4)
{
    int idx = blockIdx.x * blockDim.x + threadIdx.x;
    if (idx >= n4) return;
    int r = idx >> 7, c4 = (idx & 127) << 2;
    float4 v = ((const float4*)src)[idx];
    __half* d = dst + (size_t)r * 1024 + coloff + c4;
    ((__half2*)d)[0] = __halves2half2(__float2half(v.x), __float2half(v.y));
    ((__half2*)d)[1] = __halves2half2(__float2half(v.z), __float2half(v.w));
}

// ---------------- cp.async helper ----------------
__device__ __forceinline__ void cp16(void* s, const void* g)
{
    uint32_t sa = (uint32_t)__cvta_generic_to_shared(s);
    asm volatile("cp.async.cg.shared.global [%0], [%1], 16;\n" :: "r"(sa), "l"(g));
}

// ---------------- fp16 GEMM: C = A[M,K] * B[K,N], fp32 acc ----------------
#define SA_LD 40
#define SB_LD 136
#define STAGE_H (128*SA_LD + 32*SB_LD)
#define GEMM_SMEM (3 * STAGE_H * 2)

__global__ void __launch_bounds__(256) gemm1_kernel(
    const __half* __restrict__ A, const __half* __restrict__ B,
    float* __restrict__ C, int Nn, int K)
{
    extern __shared__ __half smh[];
    const int bm = blockIdx.y * 128;
    const int bn = blockIdx.x * 128;
    const int tid = threadIdx.x;
    const int warp = tid >> 5;
    const int wr = (warp >> 2) * 64;
    const int wc = (warp & 3) * 32;

    wmma::fragment<wmma::accumulator, 16, 16, 16, float> acc[4][2];
    #pragma unroll
    for (int i = 0; i < 4; i++)
        #pragma unroll
        for (int j = 0; j < 2; j++)
            wmma::fill_fragment(acc[i][j], 0.0f);

    auto load_st = [&](int kt) {
        __half* s = smh + (kt % 3) * STAGE_H;
        int k0 = kt << 5;
        #pragma unroll
        for (int it = 0; it < 2; ++it) {
            int v = tid + it * 256;
            int r = v >> 2, c = (v & 3) << 3;
            cp16(s + r * SA_LD + c, A + (size_t)(bm + r) * K + k0 + c);
            int rb = v >> 4, cb = (v & 15) << 3;
            cp16(s + 128 * SA_LD + rb * SB_LD + cb,
                 B + (size_t)(k0 + rb) * Nn + bn + cb);
        }
        asm volatile("cp.async.commit_group;\n");
    };

    const int nt = K >> 5;
    load_st(0);
    load_st(1);

    for (int kt = 0; kt < nt; ++kt) {
        if (kt + 1 < nt)
            asm volatile("cp.async.wait_group 1;\n");
        else
            asm volatile("cp.async.wait_group 0;\n");
        __syncthreads();
        if (kt + 2 < nt) load_st(kt + 2);

        __half* s  = smh + (kt % 3) * STAGE_H;
        __half* sA = s;
        __half* sB = s + 128 * SA_LD;

        #pragma unroll
        for (int kk = 0; kk < 32; kk += 16) {
            wmma::fragment<wmma::matrix_b, 16, 16, 16, __half, wmma::row_major> b[2];
            #pragma unroll
            for (int j = 0; j < 2; j++)
                wmma::load_matrix_sync(b[j], sB + kk * SB_LD + wc + j * 16, SB_LD);
            #pragma unroll
            for (int i = 0; i < 4; i++) {
                wmma::fragment<wmma::matrix_a, 16, 16, 16, __half, wmma::row_major> a;
                wmma::load_matrix_sync(a, sA + (wr + i * 16) * SA_LD + kk, SA_LD);
                #pragma unroll
                for (int j = 0; j < 2; j++)
                    wmma::mma_sync(acc[i][j], a, b[j], acc[i][j]);
            }
        }
        __syncthreads();
    }

    #pragma unroll
    for (int i = 0; i < 4; i++)
        #pragma unroll
        for (int j = 0; j < 2; j++)
            wmma::store_matrix_sync(C + (size_t)(bm + wr + i * 16) * Nn + bn + wc + j * 16,
                                    acc[i][j], Nn, wmma::mem_row_major);
}

// ---------------- bias add (fp32 in place) ----------------
__global__ void bias_add4_kernel(float* __restrict__ X, const float* __restrict__ b,
                                 int width, int total4)
{
    int idx = blockIdx.x * blockDim.x + threadIdx.x;
    if (idx >= total4) return;
    int c = (idx << 2) % width;
    float4 v = ((float4*)X)[idx];
    float4 bb = *(const float4*)(b + c);
    v.x += bb.x; v.y += bb.y; v.z += bb.z; v.w += bb.w;
    ((float4*)X)[idx] = v;
}

// ---------------- RoPE + bias -> fp16 hi/lo (for Q) ----------------
__global__ void rope_q_kernel(const float* __restrict__ X, const float* __restrict__ bias,
                              __half* __restrict__ Oh, __half* __restrict__ Ol,
                              int width, float scale, int total_pairs)
{
    int idx = blockIdx.x * blockDim.x + threadIdx.x;
    if (idx >= total_pairs) return;
    int ppr = width >> 1;
    int row = idx / ppr;
    int p = idx - row * ppr;
    int i = p & 63;
    int pos = row & (SEQ - 1);
    float freq = exp2f(-(float)i * 0.20762050593434293f);
    float ang = (float)pos * freq;
    float sv, cv;
    sincosf(ang, &sv, &cv);
    float2 q = *(const float2*)(X + (size_t)row * width + 2 * p);
    float e = q.x + bias[2 * p];
    float o = q.y + bias[2 * p + 1];
    float re = (e * cv - o * sv) * scale;
    float ro = (o * cv + e * sv) * scale;
    __half he = __float2half(re), ho = __float2half(ro);
    size_t off = (size_t)row * width + 2 * p;
    *(__half2*)(Oh + off) = __halves2half2(he, ho);
    *(__half2*)(Ol + off) = __halves2half2(
        __float2half(re - __half2float(he)), __float2half(ro - __half2float(ho)));
}

// ---------------- RoPE + bias -> fp16 for K ----------------
__global__ void rope_k_kernel(const float* __restrict__ KV, const float* __restrict__ bias,
                              __half* __restrict__ O, int total_pairs)
{
    int idx = blockIdx.x * blockDim.x + threadIdx.x;
    if (idx >= total_pairs) return;
    int row = idx >> 8;
    int p = idx & 255;
    int i = p & 63;
    int pos = row & (SEQ - 1);
    float freq = exp2f(-(float)i * 0.20762050593434293f);
    float ang = (float)pos * freq;
    float sv, cv;
    sincosf(ang, &sv, &cv);
    float2 q = *(const float2*)(KV + (size_t)row * 1024 + 2 * p);
    float e = q.x + bias[2 * p];
    float o = q.y + bias[2 * p + 1];
    *(__half2*)(O + (size_t)row * KVDIM + 2 * p) = __halves2half2(
        __float2half(e * cv - o * sv), __float2half(o * cv + e * sv));
}

// ---------------- bias -> fp16 for V ----------------
__global__ void bias_v_kernel(const float* __restrict__ KV, const float* __restrict__ b,
                              __half* __restrict__ O, int n4)
{
    int idx = blockIdx.x * blockDim.x + threadIdx.x;
    if (idx >= n4) return;
    int r = idx >> 7, c4 = (idx & 127) << 2;
    float4 v = *(const float4*)(KV + (size_t)r * 1024 + 512 + c4);
    float4 bb = *(const float4*)(b + c4);
    __half* d = O + (size_t)r * KVDIM + c4;
    ((__half2*)d)[0] = __halves2half2(__float2half(v.x + bb.x), __float2half(v.y + bb.y));
    ((__half2*)d)[1] = __halves2half2(__float2half(v.z + bb.z), __float2half(v.w + bb.w));
}

// ---------------- fast exp on FMA pipe ----------------
__device__ __forceinline__ float fexp(float x)
{
    float y = x * 1.4426950408889634f;
    float r = __fadd_rn(y, 12582912.0f);
    float n = __fadd_rn(r, -12582912.0f);
    float f = y - n;
    int e = __float2int_rn(n);
    e = max(e, -126); e = min(e, 126);
    float t = f * 0.6931471805599453f;
    float p = __fmaf_rn(t, 0.0083333333f, 0.041666667f);
    p = __fmaf_rn(t, p, 0.16666667f);
    p = __fmaf_rn(t, p, 0.5f);
    p = __fmaf_rn(t, p, 1.0f);
    p = __fmaf_rn(t, p, 1.0f);
    return p * __int_as_float((e + 127) << 23);
}

// ---------------- tensor-core flash attention ----------------
// 256 threads. O accumulator in registers (32 floats/thread).
// sT aliases sS (S dead before PV writes; barrier between).
#define AQ_LD 136
#define AS_LD 72
#define OQH 0
#define OQL (OQH + 64*AQ_LD*2)
#define OKK (OQL + 64*AQ_LD*2)
#define OVV (OKK + 2*64*AQ_LD*2)
#define OPP (OVV + 2*64*AQ_LD*2)
#define OST (OPP + 64*AS_LD*2)
#define ATT_SMEM (OST + 64*AQ_LD*4)

__global__ void __launch_bounds__(256) attn_tc_kernel(
    const __half* __restrict__ Qh, const __half* __restrict__ Ql,
    const __half* __restrict__ K, const __half* __restrict__ V,
    __half* __restrict__ O)
{
    extern __shared__ char smc[];
    __half* sQh = (__half*)(smc + OQH);
    __half* sQl = (__half*)(smc + OQL);
    __half* sK  = (__half*)(smc + OKK);
    __half* sV  = (__half*)(smc + OVV);
    __half* sP  = (__half*)(smc + OPP);
    float*  sS  = (float*)(smc + OST);   // aliases sT
    float*  sT  = (float*)(smc + OST);

    const int b = blockIdx.y >> 5;
    const int h = blockIdx.y & 31;
    const int kh = h & 3;
    const int q0 = blockIdx.x * 64;
    const int tid = threadIdx.x;
    const int warp = tid >> 5;

    const int wrow = (warp >> 1) * 16;
    const int wch  = (warp & 1) * 32;
    const int pch  = (warp & 1) * 64;
    const int srow = tid >> 2;
    const int quad = tid & 3;
    const int c0   = quad * 32;

    #pragma unroll
    for (int it = 0; it < 4; it++) {
        int idx = tid + it * 256;
        int r = idx >> 4, c = (idx & 15) << 3;
        size_t go = (size_t)(b * SEQ + q0 + r) * DMODEL + h * HDIM + c;
        *(uint4*)(sQh + r * AQ_LD + c) = *(const uint4*)(Qh + go);
        *(uint4*)(sQl + r * AQ_LD + c) = *(const uint4*)(Ql + go);
    }

    float oacc[32];
    #pragma unroll
    for (int c = 0; c < 32; c++) oacc[c] = 0.f;

    auto prefetch = [&](int j) {
        int buf = j & 1;
        int k0 = j * 64;
        __half* dk = sK + buf * 64 * AQ_LD;
        __half* dv = sV + buf * 64 * AQ_LD;
        #pragma unroll
        for (int i = 0; i < 4; i++) {
            int idx = tid + i * 256;
            int r = idx >> 4, c = (idx & 15) << 3;
            size_t go = (size_t)(b * SEQ + k0 + r) * KVDIM + kh * HDIM + c;
            cp16(dk + r * AQ_LD + c, K + go);
            cp16(dv + r * AQ_LD + c, V + go);
        }
        asm volatile("cp.async.commit_group;\n");
    };

    prefetch(0);

    float mrow = -1e30f, lrow = 0.f;

    const int jmax = blockIdx.x;
    for (int j = 0; j <= jmax; ++j) {
        asm volatile("cp.async.wait_group 0;\n");
        __syncthreads();
        if (j + 1 <= jmax) prefetch(j + 1);

        __half* cK = sK + (j & 1) * 64 * AQ_LD;
        __half* cV = sV + (j & 1) * 64 * AQ_LD;

        // ---- S = Q K^T (hi + lo) ----
        {
            wmma::fragment<wmma::accumulator, 16, 16, 16, float> acc[2];
            wmma::fill_fragment(acc[0], 0.f);
            wmma::fill_fragment(acc[1], 0.f);
            #pragma unroll
            for (int ks = 0; ks < 8; ks++) {
                wmma::fragment<wmma::matrix_a, 16, 16, 16, __half, wmma::row_major> ah, al;
                wmma::load_matrix_sync(ah, sQh + wrow * AQ_LD + ks * 16, AQ_LD);
                wmma::load_matrix_sync(al, sQl + wrow * AQ_LD + ks * 16, AQ_LD);
                #pragma unroll
                for (int nf = 0; nf < 2; nf++) {
                    wmma::fragment<wmma::matrix_b, 16, 16, 16, __half, wmma::col_major> bf;
                    wmma::load_matrix_sync(bf, cK + (wch + nf * 16) * AQ_LD + ks * 16, AQ_LD);
                    wmma::mma_sync(acc[nf], ah, bf, acc[nf]);
                    wmma::mma_sync(acc[nf], al, bf, acc[nf]);
                }
            }
            #pragma unroll
            for (int nf = 0; nf < 2; nf++)
                wmma::store_matrix_sync(sS + wrow * AS_LD + wch + nf * 16, acc[nf],
                                        AS_LD, wmma::mem_row_major);
        }
        __syncthreads();

        // ---- online softmax (4 threads/row) ----
        float alpha;
        {
            const int cbase = quad * 16;
            const bool diag = (j == jmax);
            float sv[16];
            float mx = -1e30f;
            #pragma unroll
            for (int c = 0; c < 16; c++) {
                float s = sS[srow * AS_LD + cbase + c];
                if (diag && (cbase + c > srow)) s = -1e30f;
                sv[c] = s;
                mx = fmaxf(mx, s);
            }
            mx = fmaxf(mx, __shfl_xor_sync(0xffffffffu, mx, 1));
            mx = fmaxf(mx, __shfl_xor_sync(0xffffffffu, mx, 2));
            float mnew = fmaxf(mrow, mx);
            alpha = fexp(mrow - mnew);
            float sum = 0.f;
            #pragma unroll
            for (int c = 0; c < 16; c++) {
                float p = fexp(sv[c] - mnew);
                sP[srow * AS_LD + cbase + c] = __float2half(p);
                sum += p;
            }
            sum += __shfl_xor_sync(0xffffffffu, sum, 1);
            sum += __shfl_xor_sync(0xffffffffu, sum, 2);
            lrow = lrow * alpha + sum;
            mrow = mnew;
        }
        __syncthreads();   // sP ready; sS dead -> sT may be written

        // ---- T = P V ----
        {
            wmma::fragment<wmma::accumulator, 16, 16, 16, float> acc[4];
            #pragma unroll
            for (int nf = 0; nf < 4; nf++) wmma::fill_fragment(acc[nf], 0.f);
            #pragma unroll
            for (int kf = 0; kf < 4; kf++) {
                wmma::fragment<wmma::matrix_a, 16, 16, 16, __half, wmma::row_major> af;
                wmma::load_matrix_sync(af, sP + wrow * AS_LD + kf * 16, AS_LD);
                #pragma unroll
                for (int nf = 0; nf < 4; nf++) {
                    wmma::fragment<wmma::matrix_b, 16, 16, 16, __half, wmma::row_major> bf;
                    wmma::load_matrix_sync(bf, cV + kf * 16 * AQ_LD + pch + nf * 16, AQ_LD);
                    wmma::mma_sync(acc[nf], af, bf, acc[nf]);
                }
            }
            #pragma unroll
            for (int nf = 0; nf < 4; nf++)
                wmma::store_matrix_sync(sT + wrow * AQ_LD + pch + nf * 16, acc[nf],
                                        AQ_LD, wmma::mem_row_major);
        }
        __syncthreads();

        // ---- O(regs) = O*alpha + T ----
        {
            #pragma unroll
            for (int c = 0; c < 32; c += 4) {
                float4 t = *(float4*)(sT + srow * AQ_LD + c0 + c);
                oacc[c]     = oacc[c]     * alpha + t.x;
                oacc[c + 1] = oacc[c + 1] * alpha + t.y;
                oacc[c + 2] = oacc[c + 2] * alpha + t.z;
                oacc[c + 3] = oacc[c + 3] * alpha + t.w;
            }
        }
        __syncthreads();   // protect sT (= next iter's sS) until all reads done
    }

    // final write from registers
    {
        float inv = 1.f / lrow;
        size_t off = (size_t)(b * SEQ + q0 + srow) * DMODEL + h * HDIM + c0;
        #pragma unroll
        for (int c = 0; c < 32; c += 2) {
            *(__half2*)(O + off + c) = __halves2half2(
                __float2half(oacc[c] * inv), __float2half(oacc[c + 1] * inv));
        }
    }
}

// ---------------- launch ----------------
extern "C" void kernel_launch(void* const* d_in, const int* in_sizes, int n_in,
                              void* d_out, int out_size)
{
    const float* x  = (const float*)d_in[0];
    const float* Wq = (const float*)d_in[1];
    const float* bq = (const float*)d_in[2];
    const float* Wk = (const float*)d_in[3];
    const float* bk = (const float*)d_in[4];
    const float* Wv = (const float*)d_in[5];
    const float* bv = (const float*)d_in[6];
    const float* Wo = (const float*)d_in[7];
    const float* bo = (const float*)d_in[8];
    float* out = (float*)d_out;

    float *Qp, *KVp;
    __half *xp, *wq, *wkv, *wo, *op, *qh, *ql, *kk, *vv;
    cudaGetSymbolAddress((void**)&Qp, g_Q);
    cudaGetSymbolAddress((void**)&KVp, g_KV);
    cudaGetSymbolAddress((void**)&xp, g_x);
    cudaGetSymbolAddress((void**)&wq, g_wq);
    cudaGetSymbolAddress((void**)&wkv, g_wkv);
    cudaGetSymbolAddress((void**)&wo, g_wo);
    cudaGetSymbolAddress((void**)&op, g_o);
    cudaGetSymbolAddress((void**)&qh, g_Qh); cudaGetSymbolAddress((void**)&ql, g_Ql);
    cudaGetSymbolAddress((void**)&kk, g_Kh); cudaGetSymbolAddress((void**)&vv, g_Vh);

    cudaFuncSetAttribute(gemm1_kernel, cudaFuncAttributeMaxDynamicSharedMemorySize, GEMM_SMEM);
    cudaFuncSetAttribute(attn_tc_kernel, cudaFuncAttributeMaxDynamicSharedMemorySize, ATT_SMEM);

    cudaStream_t s1;
    cudaStreamCreate(&s1);
    cudaEvent_t eFork, eJoin;
    cudaEventCreateWithFlags(&eFork, cudaEventDisableTiming);
    cudaEventCreateWithFlags(&eJoin, cudaEventDisableTiming);

    // x conversion (needed by both chains)
    {
        int n4 = MROWS * DMODEL / 4;
        conv_half_kernel<<<(n4 + 255) / 256, 256>>>(x, xp, n4);
    }

    // fork
    cudaEventRecord(eFork, 0);
    cudaStreamWaitEvent(s1, eFork, 0);

    const float scale = 0.08838834764831843f;

    // default stream: Wq conv -> Q gemm -> rope_q
    {
        int n4 = DMODEL * DMODEL / 4;
        conv_half_kernel<<<(n4 + 255) / 256, 256>>>(Wq, wq, n4);
    }
    gemm1_kernel<<<dim3(DMODEL / 128, MROWS / 128), 256, GEMM_SMEM>>>(
        xp, wq, Qp, DMODEL, DMODEL);
    {
        int tpQ = MROWS * (DMODEL / 2);
        rope_q_kernel<<<(tpQ + 255) / 256, 256>>>(Qp, bq, qh, ql, DMODEL, scale, tpQ);
    }

    // s1: Wk/Wv pack -> KV gemm -> rope_k, bias_v, Wo conv
    {
        int n4 = DMODEL * KVDIM / 4;
        conv_half_pack_kernel<<<(n4 + 255) / 256, 256, 0, s1>>>(Wk, wkv, 0,   n4);
        conv_half_pack_kernel<<<(n4 + 255) / 256, 256, 0, s1>>>(Wv, wkv, 512, n4);
    }
    gemm1_kernel<<<dim3(1024 / 128, MROWS / 128), 256, GEMM_SMEM, s1>>>(
        xp, wkv, KVp, 1024, DMODEL);
    {
        int tpK = MROWS * 256;
        rope_k_kernel<<<(tpK + 255) / 256, 256, 0, s1>>>(KVp, bk, kk, tpK);
        int n4v = MROWS * KVDIM / 4;
        bias_v_kernel<<<(n4v + 255) / 256, 256, 0, s1>>>(KVp, bv, vv, n4v);
        int n4o = DMODEL * DMODEL / 4;
        conv_half_kernel<<<(n4o + 255) / 256, 256, 0, s1>>>(Wo, wo, n4o);
    }

    // join
    cudaEventRecord(eJoin, s1);
    cudaStreamWaitEvent(0, eJoin, 0);

    // attention (tensor cores, single launch)
    attn_tc_kernel<<<dim3(SEQ / 64, BATCH * NHEAD), 256, ATT_SMEM>>>(qh, ql, kk, vv, op);

    // output projection + bias
    gemm1_kernel<<<dim3(DMODEL / 128, MROWS / 128), 256, GEMM_SMEM>>>(
        op, wo, out, DMODEL, DMODEL);
    {
        int t4 = MROWS * DMODEL / 4;
        bias_add4_kernel<<<(t4 + 255) / 256, 256>>>(out, bo, DMODEL, t4);
    }

    cudaEventDestroy(eFork);
    cudaEventDestroy(eJoin);
    cudaStreamDestroy(s1);
}